// round 5
// baseline (speedup 1.0000x reference)
#include <cuda_runtime.h>
#include <cstddef>

// ---------------------------------------------------------------------------
// Problem constants
// ---------------------------------------------------------------------------
#define DIMC   384
#define NHEADS 12
#define HD     32
#define NTOK   49          // window size 7x7
#define NWIN   64
#define BATCH  4096
#define MROWS  (BATCH * NTOK)   // 200704 = 128 * 1568

// ---------------------------------------------------------------------------
// Scratch (static device globals: allocation-guard safe)
// ---------------------------------------------------------------------------
__device__ float g_qp[(size_t)MROWS * DIMC];        // q projection   [M, 384]
__device__ float g_kv[(size_t)MROWS * 2 * DIMC];    // kv projection  [M, 768] (k | v)
__device__ float g_ao[(size_t)MROWS * DIMC];        // attention out  [M, 384]

// ---------------------------------------------------------------------------
// Tiled fp32 GEMM with bias:  C[M,N] = A[M,K] @ B[K,N] + bias[N]
// BM=128, BN=64, BK=16, per-thread 8x4, 256 threads.
// Requires M%128==0, N%64==0, K%16==0 (true for all three calls).
// ---------------------------------------------------------------------------
#define BM 128
#define BN 64
#define BK 16
#define TM 8
#define TN 4
#define AS_STRIDE (BM + 4)   // padded to reduce store bank conflicts

__global__ __launch_bounds__(256, 2) void gemm_bias_kernel(
    const float* __restrict__ A, const float* __restrict__ B,
    const float* __restrict__ bias, float* __restrict__ C,
    int M, int N, int K)
{
    __shared__ float As[BK * AS_STRIDE];   // transposed: As[k][m]
    __shared__ float Bs[BK * BN];          // Bs[k][n]

    const int tid = threadIdx.x;
    const int tx  = tid & 15;              // 16 cols of threads (BN/TN)
    const int ty  = tid >> 4;              // 16 rows of threads (BM/TM)
    const int rowBase = blockIdx.y * BM;
    const int colBase = blockIdx.x * BN;

    float acc[TM][TN];
    #pragma unroll
    for (int i = 0; i < TM; i++)
        #pragma unroll
        for (int j = 0; j < TN; j++) acc[i][j] = 0.f;

    for (int k0 = 0; k0 < K; k0 += BK) {
        // --- load A tile (BM x BK): 512 float4, 2 per thread, transpose into smem
        #pragma unroll
        for (int r = 0; r < 2; r++) {
            int f    = tid + r * 256;      // float4 id within tile
            int arow = f >> 2;             // 0..127
            int ac4  = f & 3;              // 0..3  (16/4)
            float4 va = *reinterpret_cast<const float4*>(
                &A[(size_t)(rowBase + arow) * K + k0 + ac4 * 4]);
            As[(ac4 * 4 + 0) * AS_STRIDE + arow] = va.x;
            As[(ac4 * 4 + 1) * AS_STRIDE + arow] = va.y;
            As[(ac4 * 4 + 2) * AS_STRIDE + arow] = va.z;
            As[(ac4 * 4 + 3) * AS_STRIDE + arow] = va.w;
        }
        // --- load B tile (BK x BN): 256 float4, 1 per thread
        {
            int brow = tid >> 4;           // 0..15
            int bc4  = tid & 15;           // 0..15
            *reinterpret_cast<float4*>(&Bs[brow * BN + bc4 * 4]) =
                *reinterpret_cast<const float4*>(
                    &B[(size_t)(k0 + brow) * N + colBase + bc4 * 4]);
        }
        __syncthreads();

        #pragma unroll
        for (int kk = 0; kk < BK; kk++) {
            float a[TM], bb[TN];
            #pragma unroll
            for (int i = 0; i < TM; i += 4) {
                float4 v = *reinterpret_cast<const float4*>(
                    &As[kk * AS_STRIDE + ty * TM + i]);
                a[i] = v.x; a[i + 1] = v.y; a[i + 2] = v.z; a[i + 3] = v.w;
            }
            {
                float4 v = *reinterpret_cast<const float4*>(
                    &Bs[kk * BN + tx * TN]);
                bb[0] = v.x; bb[1] = v.y; bb[2] = v.z; bb[3] = v.w;
            }
            #pragma unroll
            for (int i = 0; i < TM; i++)
                #pragma unroll
                for (int j = 0; j < TN; j++)
                    acc[i][j] = fmaf(a[i], bb[j], acc[i][j]);
        }
        __syncthreads();
    }

    // --- epilogue: bias add, vectorized store
    float4 bv = *reinterpret_cast<const float4*>(&bias[colBase + tx * TN]);
    #pragma unroll
    for (int i = 0; i < TM; i++) {
        float4 v;
        v.x = acc[i][0] + bv.x;
        v.y = acc[i][1] + bv.y;
        v.z = acc[i][2] + bv.z;
        v.w = acc[i][3] + bv.w;
        *reinterpret_cast<float4*>(
            &C[(size_t)(rowBase + ty * TM + i) * N + colBase + tx * TN]) = v;
    }
}

// ---------------------------------------------------------------------------
// Fused window attention: one block per (window b, head h).
//   logits = scale * q k^T + bias_table[rel_index][h] + mask[b%64]
//   softmax over last dim, then P @ V
// ---------------------------------------------------------------------------
__global__ __launch_bounds__(256) void attn_kernel(
    const float* __restrict__ qp, const float* __restrict__ kvp,
    const float* __restrict__ mask, const float* __restrict__ bias_table,
    const int* __restrict__ rel_index, float* __restrict__ ao)
{
    const int b   = blockIdx.x;
    const int h   = blockIdx.y;
    const int tid = threadIdx.x;

    __shared__ float qs[NTOK * 33];   // padded rows -> conflict-free
    __shared__ float ks[NTOK * 33];
    __shared__ float vs[NTOK * 33];
    __shared__ float sa[NTOK * 50];   // logits / probabilities

    // load q/k/v tiles for this (b,h)
    for (int idx = tid; idx < NTOK * HD; idx += 256) {
        int r = idx >> 5, c = idx & 31;
        size_t qoff  = (size_t)(b * NTOK + r) * DIMC + h * HD + c;
        size_t kvoff = (size_t)(b * NTOK + r) * (2 * DIMC) + h * HD + c;
        qs[r * 33 + c] = qp[qoff];
        ks[r * 33 + c] = kvp[kvoff];
        vs[r * 33 + c] = kvp[kvoff + DIMC];
    }
    __syncthreads();

    const float scale = 0.17677669529663687f;   // 32^{-1/2}
    const float* mptr = mask + (size_t)(b & (NWIN - 1)) * NTOK * NTOK;

    // logits: 2401 entries, ~10 per thread
    for (int e = tid; e < NTOK * NTOK; e += 256) {
        int n = e / NTOK, m = e - n * NTOK;
        float s = 0.f;
        #pragma unroll
        for (int d = 0; d < HD; d++)
            s = fmaf(qs[n * 33 + d], ks[m * 33 + d], s);
        s = fmaf(s, scale, bias_table[rel_index[e] * NHEADS + h] + mptr[e]);
        sa[n * 50 + m] = s;
    }
    __syncthreads();

    // softmax: one thread per row
    if (tid < NTOK) {
        float mx = -1e30f;
        #pragma unroll 7
        for (int m = 0; m < NTOK; m++) mx = fmaxf(mx, sa[tid * 50 + m]);
        float sum = 0.f;
        #pragma unroll 7
        for (int m = 0; m < NTOK; m++) {
            float ev = __expf(sa[tid * 50 + m] - mx);
            sa[tid * 50 + m] = ev;
            sum += ev;
        }
        float inv = 1.f / sum;
        #pragma unroll 7
        for (int m = 0; m < NTOK; m++) sa[tid * 50 + m] *= inv;
    }
    __syncthreads();

    // out = P @ V : 1568 entries, ~6 per thread
    for (int e = tid; e < NTOK * HD; e += 256) {
        int n = e >> 5, d = e & 31;
        float s = 0.f;
        #pragma unroll 7
        for (int m = 0; m < NTOK; m++)
            s = fmaf(sa[n * 50 + m], vs[m * 33 + d], s);
        ao[(size_t)(b * NTOK + n) * DIMC + h * HD + d] = s;
    }
}

// ---------------------------------------------------------------------------
// Launch
// ---------------------------------------------------------------------------
extern "C" void kernel_launch(void* const* d_in, const int* in_sizes, int n_in,
                              void* d_out, int out_size)
{
    const float* q          = (const float*)d_in[0];
    const float* kv         = (const float*)d_in[1];
    const float* mask       = (const float*)d_in[2];
    const float* Wq         = (const float*)d_in[3];
    const float* bq         = (const float*)d_in[4];
    const float* Wkv        = (const float*)d_in[5];
    const float* bkv        = (const float*)d_in[6];
    const float* Wp         = (const float*)d_in[7];
    const float* bp         = (const float*)d_in[8];
    const float* bias_table = (const float*)d_in[9];
    const int*   rel_index  = (const int*)d_in[10];
    float*       out        = (float*)d_out;

    float *qp, *kvp, *ao;
    cudaGetSymbolAddress((void**)&qp,  g_qp);
    cudaGetSymbolAddress((void**)&kvp, g_kv);
    cudaGetSymbolAddress((void**)&ao,  g_ao);

    const int mblocks = MROWS / BM;   // 1568

    // 1. q projection: [M,384] = q @ Wq + bq
    gemm_bias_kernel<<<dim3(DIMC / BN, mblocks), 256>>>(
        q, Wq, bq, qp, MROWS, DIMC, DIMC);

    // 2. kv projection: [M,768] = kv @ Wkv + bkv
    gemm_bias_kernel<<<dim3(2 * DIMC / BN, mblocks), 256>>>(
        kv, Wkv, bkv, kvp, MROWS, 2 * DIMC, DIMC);

    // 3. fused window attention
    attn_kernel<<<dim3(BATCH, NHEADS), 256>>>(
        qp, kvp, mask, bias_table, rel_index, ao);

    // 4. output projection: out = ao @ Wp + bp
    gemm_bias_kernel<<<dim3(DIMC / BN, mblocks), 256>>>(
        ao, Wp, bp, out, MROWS, DIMC, DIMC);
}

// round 10
// speedup vs baseline: 1.6938x; 1.6938x over previous
#include <cuda_runtime.h>
#include <cstdint>
#include <cstddef>

// ---------------------------------------------------------------------------
// Problem constants
// ---------------------------------------------------------------------------
#define DIMC   384
#define NHEADS 12
#define HD     32
#define NTOK   49
#define NWIN   64
#define BATCH  4096
#define MROWS  (BATCH * NTOK)   // 200704 = 128 * 1568

// ---------------------------------------------------------------------------
// Scratch (static device globals: allocation-guard safe)
// ---------------------------------------------------------------------------
__device__ float g_qp[(size_t)MROWS * DIMC];
__device__ float g_kv[(size_t)MROWS * 2 * DIMC];
__device__ float g_ao[(size_t)MROWS * DIMC];
__device__ float g_wqt[DIMC * DIMC];          // Wq^T  [N,K]
__device__ float g_wkvt[2 * DIMC * DIMC];     // Wkv^T [N,K]
__device__ float g_wpt[DIMC * DIMC];          // Wp^T  [N,K]

// ---------------------------------------------------------------------------
// TF32 helpers (baseline PTX, works on plain sm_103 target)
// ---------------------------------------------------------------------------
__device__ __forceinline__ uint32_t f2tf32(float x) {
    uint32_t r;
    asm("cvt.rna.tf32.f32 %0, %1;" : "=r"(r) : "f"(x));
    return r;
}

__device__ __forceinline__ void mma_tf32(float c[4], const uint32_t a[4],
                                         const uint32_t b[2]) {
    asm volatile(
        "mma.sync.aligned.m16n8k8.row.col.f32.tf32.tf32.f32 "
        "{%0,%1,%2,%3}, {%4,%5,%6,%7}, {%8,%9}, {%0,%1,%2,%3};"
        : "+f"(c[0]), "+f"(c[1]), "+f"(c[2]), "+f"(c[3])
        : "r"(a[0]), "r"(a[1]), "r"(a[2]), "r"(a[3]), "r"(b[0]), "r"(b[1]));
}

// ---------------------------------------------------------------------------
// Weight transpose:  dst[N,K] = src[K,N]   (K,N multiples of 32)
// ---------------------------------------------------------------------------
__global__ void transpose_kernel(const float* __restrict__ src,
                                 float* __restrict__ dst, int K, int N)
{
    __shared__ float t[32][33];
    int bx = blockIdx.x * 32;   // N dim
    int by = blockIdx.y * 32;   // K dim
    #pragma unroll
    for (int i = 0; i < 32; i += 8)
        t[threadIdx.y + i][threadIdx.x] =
            src[(size_t)(by + threadIdx.y + i) * N + bx + threadIdx.x];
    __syncthreads();
    #pragma unroll
    for (int i = 0; i < 32; i += 8)
        dst[(size_t)(bx + threadIdx.y + i) * K + by + threadIdx.x] =
            t[threadIdx.x][threadIdx.y + i];
}

// ---------------------------------------------------------------------------
// TF32 tensor-core GEMM with bias:  C[M,N] = A[M,K] @ Bt[N,K]^T + bias[N]
//
// CTA tile 128x128, K-chunk 32, 256 threads = 8 warps, warp tile 64x32.
// SMEM holds operands in *fragment-major* layout so readers use one
// LDS.128 (A) / LDS.64 (B) per mma fragment, conflict-free:
//   A:  [mg 0..7][s 0..3] blocks of (32 lanes x 4 regs), block stride 136 u32
//   B:  [ng 0..15][s 0..3] blocks of (32 lanes x 2 regs), block stride 80 u32
// where for m16n8k8.row.col, lane = g*4+tig and
//   A regs: a0=(g,tig) a1=(g+8,tig) a2=(g,tig+4) a3=(g+8,tig+4)   [row,col in 16x8]
//   B regs: b0=(k=tig,n=g) b1=(k=tig+4,n=g)                        [8x8]
// cvt.rna.tf32 is applied by the writer.
// Requires M%128==0, N%128==0, K%32==0.
// ---------------------------------------------------------------------------
#define GBM 128
#define GBN 128
#define GBK 32
#define A_BLK 136   // padded block stride (u32) — breaks s-stride bank collisions
#define B_BLK 80

__global__ __launch_bounds__(256, 2) void gemm_mma_kernel(
    const float* __restrict__ A, const float* __restrict__ Bt,
    const float* __restrict__ bias, float* __restrict__ C,
    int M, int N, int K)
{
    __shared__ uint32_t As[32 * A_BLK];   // 8 mg * 4 s blocks  (17408 B)
    __shared__ uint32_t Bs[64 * B_BLK];   // 16 ng * 4 s blocks (20480 B)

    const int tid  = threadIdx.x;
    const int wid  = tid >> 5;
    const int lane = tid & 31;
    const int wm   = wid & 1;      // 2 m-warps (64 rows each)
    const int wn   = wid >> 1;     // 4 n-warps (32 cols each)
    const int g    = lane >> 2;
    const int tig  = lane & 3;
    const int rowBase = blockIdx.y * GBM;
    const int colBase = blockIdx.x * GBN;

    float acc[4][4][4];
    #pragma unroll
    for (int i = 0; i < 4; i++)
        #pragma unroll
        for (int j = 0; j < 4; j++)
            #pragma unroll
            for (int r = 0; r < 4; r++) acc[i][j][r] = 0.f;

    const int nchunks = K / GBK;
    for (int c = 0; c < nchunks; c++) {
        if (c) __syncthreads();

        // ---- writer: 128x32 A tile + 128x32 B tile, fragment-major + tf32 cvt
        const float* Ag = A  + (size_t)rowBase * K + c * GBK;
        const float* Bg = Bt + (size_t)colBase * K + c * GBK;
        #pragma unroll
        for (int i = 0; i < 4; i++) {
            int f   = i * 256 + tid;      // 1024 float4 per tile
            int row = f >> 3;             // 0..127
            int c4  = f & 7;              // float4 within 32-wide row
            float4 va = *reinterpret_cast<const float4*>(Ag + (size_t)row * K + c4 * 4);
            float4 vb = *reinterpret_cast<const float4*>(Bg + (size_t)row * K + c4 * 4);
            int s  = c4 >> 1;             // k-step 0..3
            int rb = c4 & 1;              // high-half-of-8 bit
            // A: mg = row>>4, within-frag row bit -> reg bit0, rb -> reg bit1
            {
                int mg = row >> 4, hi = (row >> 3) & 1, ga = row & 7;
                int base = (mg * 4 + s) * A_BLK + ga * 16 + (hi | (rb << 1));
                As[base +  0] = f2tf32(va.x);
                As[base +  4] = f2tf32(va.y);
                As[base +  8] = f2tf32(va.z);
                As[base + 12] = f2tf32(va.w);
            }
            // B: ng = row>>3, rb -> reg index
            {
                int ng = row >> 3, gb = row & 7;
                int base = (ng * 4 + s) * B_BLK + gb * 8 + rb;
                Bs[base + 0] = f2tf32(vb.x);
                Bs[base + 2] = f2tf32(vb.y);
                Bs[base + 4] = f2tf32(vb.z);
                Bs[base + 6] = f2tf32(vb.w);
            }
        }
        __syncthreads();

        // ---- compute: 4 k-steps x (4 mfrag x 4 nfrag) mma
        #pragma unroll
        for (int s = 0; s < 4; s++) {
            uint32_t af[4][4], bf[4][2];
            #pragma unroll
            for (int mf = 0; mf < 4; mf++) {
                uint4 v = *reinterpret_cast<const uint4*>(
                    &As[((wm * 4 + mf) * 4 + s) * A_BLK + lane * 4]);
                af[mf][0] = v.x; af[mf][1] = v.y; af[mf][2] = v.z; af[mf][3] = v.w;
            }
            #pragma unroll
            for (int nf = 0; nf < 4; nf++) {
                uint2 v = *reinterpret_cast<const uint2*>(
                    &Bs[((wn * 4 + nf) * 4 + s) * B_BLK + lane * 2]);
                bf[nf][0] = v.x; bf[nf][1] = v.y;
            }
            #pragma unroll
            for (int mf = 0; mf < 4; mf++)
                #pragma unroll
                for (int nf = 0; nf < 4; nf++)
                    mma_tf32(acc[mf][nf], af[mf], bf[nf]);
        }
    }

    // ---- epilogue: bias add + STG.64
    #pragma unroll
    for (int nf = 0; nf < 4; nf++) {
        int col = colBase + wn * 32 + nf * 8 + tig * 2;
        float2 bv = *reinterpret_cast<const float2*>(bias + col);
        #pragma unroll
        for (int mf = 0; mf < 4; mf++) {
            int row0 = rowBase + wm * 64 + mf * 16 + g;
            float2 v0 = { acc[mf][nf][0] + bv.x, acc[mf][nf][1] + bv.y };
            float2 v1 = { acc[mf][nf][2] + bv.x, acc[mf][nf][3] + bv.y };
            *reinterpret_cast<float2*>(C + (size_t)row0 * N + col)       = v0;
            *reinterpret_cast<float2*>(C + (size_t)(row0 + 8) * N + col) = v1;
        }
    }
}

// ---------------------------------------------------------------------------
// Fused window attention (unchanged from passing version)
// ---------------------------------------------------------------------------
__global__ __launch_bounds__(256) void attn_kernel(
    const float* __restrict__ qp, const float* __restrict__ kvp,
    const float* __restrict__ mask, const float* __restrict__ bias_table,
    const int* __restrict__ rel_index, float* __restrict__ ao)
{
    const int b   = blockIdx.x;
    const int h   = blockIdx.y;
    const int tid = threadIdx.x;

    __shared__ float qs[NTOK * 33];
    __shared__ float ks[NTOK * 33];
    __shared__ float vs[NTOK * 33];
    __shared__ float sa[NTOK * 50];

    for (int idx = tid; idx < NTOK * HD; idx += 256) {
        int r = idx >> 5, c = idx & 31;
        size_t qoff  = (size_t)(b * NTOK + r) * DIMC + h * HD + c;
        size_t kvoff = (size_t)(b * NTOK + r) * (2 * DIMC) + h * HD + c;
        qs[r * 33 + c] = qp[qoff];
        ks[r * 33 + c] = kvp[kvoff];
        vs[r * 33 + c] = kvp[kvoff + DIMC];
    }
    __syncthreads();

    const float scale = 0.17677669529663687f;
    const float* mptr = mask + (size_t)(b & (NWIN - 1)) * NTOK * NTOK;

    for (int e = tid; e < NTOK * NTOK; e += 256) {
        int n = e / NTOK, m = e - n * NTOK;
        float s = 0.f;
        #pragma unroll
        for (int d = 0; d < HD; d++)
            s = fmaf(qs[n * 33 + d], ks[m * 33 + d], s);
        s = fmaf(s, scale, bias_table[rel_index[e] * NHEADS + h] + mptr[e]);
        sa[n * 50 + m] = s;
    }
    __syncthreads();

    if (tid < NTOK) {
        float mx = -1e30f;
        #pragma unroll 7
        for (int m = 0; m < NTOK; m++) mx = fmaxf(mx, sa[tid * 50 + m]);
        float sum = 0.f;
        #pragma unroll 7
        for (int m = 0; m < NTOK; m++) {
            float ev = __expf(sa[tid * 50 + m] - mx);
            sa[tid * 50 + m] = ev;
            sum += ev;
        }
        float inv = 1.f / sum;
        #pragma unroll 7
        for (int m = 0; m < NTOK; m++) sa[tid * 50 + m] *= inv;
    }
    __syncthreads();

    for (int e = tid; e < NTOK * HD; e += 256) {
        int n = e >> 5, d = e & 31;
        float s = 0.f;
        #pragma unroll 7
        for (int m = 0; m < NTOK; m++)
            s = fmaf(sa[n * 50 + m], vs[m * 33 + d], s);
        ao[(size_t)(b * NTOK + n) * DIMC + h * HD + d] = s;
    }
}

// ---------------------------------------------------------------------------
// Launch
// ---------------------------------------------------------------------------
extern "C" void kernel_launch(void* const* d_in, const int* in_sizes, int n_in,
                              void* d_out, int out_size)
{
    const float* q          = (const float*)d_in[0];
    const float* kv         = (const float*)d_in[1];
    const float* mask       = (const float*)d_in[2];
    const float* Wq         = (const float*)d_in[3];
    const float* bq         = (const float*)d_in[4];
    const float* Wkv        = (const float*)d_in[5];
    const float* bkv        = (const float*)d_in[6];
    const float* Wp         = (const float*)d_in[7];
    const float* bp         = (const float*)d_in[8];
    const float* bias_table = (const float*)d_in[9];
    const int*   rel_index  = (const int*)d_in[10];
    float*       out        = (float*)d_out;

    float *qp, *kvp, *ao, *wqt, *wkvt, *wpt;
    cudaGetSymbolAddress((void**)&qp,   g_qp);
    cudaGetSymbolAddress((void**)&kvp,  g_kv);
    cudaGetSymbolAddress((void**)&ao,   g_ao);
    cudaGetSymbolAddress((void**)&wqt,  g_wqt);
    cudaGetSymbolAddress((void**)&wkvt, g_wkvt);
    cudaGetSymbolAddress((void**)&wpt,  g_wpt);

    // 0. transpose weights to [N,K]
    transpose_kernel<<<dim3(DIMC / 32, DIMC / 32), dim3(32, 8)>>>(Wq, wqt, DIMC, DIMC);
    transpose_kernel<<<dim3(2 * DIMC / 32, DIMC / 32), dim3(32, 8)>>>(Wkv, wkvt, DIMC, 2 * DIMC);
    transpose_kernel<<<dim3(DIMC / 32, DIMC / 32), dim3(32, 8)>>>(Wp, wpt, DIMC, DIMC);

    const int mblocks = MROWS / GBM;   // 1568

    // 1. q projection
    gemm_mma_kernel<<<dim3(DIMC / GBN, mblocks), 256>>>(
        q, wqt, bq, qp, MROWS, DIMC, DIMC);

    // 2. kv projection
    gemm_mma_kernel<<<dim3(2 * DIMC / GBN, mblocks), 256>>>(
        kv, wkvt, bkv, kvp, MROWS, 2 * DIMC, DIMC);

    // 3. fused window attention
    attn_kernel<<<dim3(BATCH, NHEADS), 256>>>(
        qp, kvp, mask, bias_table, rel_index, ao);

    // 4. output projection
    gemm_mma_kernel<<<dim3(DIMC / GBN, mblocks), 256>>>(
        ao, wpt, bp, out, MROWS, DIMC, DIMC);
}

// round 15
// speedup vs baseline: 2.5898x; 1.5290x over previous
#include <cuda_runtime.h>
#include <cstdint>
#include <cstddef>

// ---------------------------------------------------------------------------
// Problem constants
// ---------------------------------------------------------------------------
#define DIMC   384
#define NHEADS 12
#define HD     32
#define NTOK   49
#define NWIN   64
#define BATCH  4096
#define MROWS  (BATCH * NTOK)   // 200704 = 128 * 1568

// ---------------------------------------------------------------------------
// Scratch (static device globals: allocation-guard safe)
// ---------------------------------------------------------------------------
__device__ float    g_qp[(size_t)MROWS * DIMC];
__device__ float    g_kv[(size_t)MROWS * 2 * DIMC];
__device__ float    g_ao[(size_t)MROWS * DIMC];
__device__ uint32_t g_wqp[DIMC * DIMC];            // Wq  fragment-major tf32
__device__ uint32_t g_wkvp[2 * DIMC * DIMC];       // Wkv fragment-major tf32
__device__ uint32_t g_wpp[DIMC * DIMC];            // Wp  fragment-major tf32
__device__ float    g_cmb[NWIN * NHEADS * NTOK * NTOK];  // mask+bias combined

// ---------------------------------------------------------------------------
// Helpers (baseline PTX only — plain sm_103 target)
// ---------------------------------------------------------------------------
__device__ __forceinline__ uint32_t f2tf32(float x) {
    uint32_t r;
    asm("cvt.rna.tf32.f32 %0, %1;" : "=r"(r) : "f"(x));
    return r;
}

__device__ __forceinline__ void mma_tf32(float c[4], const uint32_t a[4],
                                         const uint32_t b[2]) {
    asm volatile(
        "mma.sync.aligned.m16n8k8.row.col.f32.tf32.tf32.f32 "
        "{%0,%1,%2,%3}, {%4,%5,%6,%7}, {%8,%9}, {%0,%1,%2,%3};"
        : "+f"(c[0]), "+f"(c[1]), "+f"(c[2]), "+f"(c[3])
        : "r"(a[0]), "r"(a[1]), "r"(a[2]), "r"(a[3]), "r"(b[0]), "r"(b[1]));
}

__device__ __forceinline__ uint32_t smem_u32(const void* p) {
    uint32_t a;
    asm("{ .reg .u64 t; cvta.to.shared.u64 t, %1; cvt.u32.u64 %0, t; }"
        : "=r"(a) : "l"(p));
    return a;
}

__device__ __forceinline__ void cp_async16(uint32_t dst_smem, const void* src) {
    asm volatile("cp.async.cg.shared.global [%0], [%1], 16;"
                 :: "r"(dst_smem), "l"(src) : "memory");
}
__device__ __forceinline__ void cp_commit() {
    asm volatile("cp.async.commit_group;" ::: "memory");
}
__device__ __forceinline__ void cp_wait_all() {
    asm volatile("cp.async.wait_group 0;" ::: "memory");
}

// ---------------------------------------------------------------------------
// prep_weights: W row-major [K,N] -> fragment-major tf32 global.
// Per (n-block j of 128, k-chunk c of 32): 4096-u32 image, index
//   (ng*4 + s)*64 + gb*8 + tig*2 + rb
// with ng=(n>>3)&15, gb=n&7, s=(k>>3)&3, rb=(k>>2)&1, tig=k&3.
// Verified against the reader: uint2 at lane*2 = g*8 + tig*2 gives
// b0 = (k=s*8+tig, n=g), b1 = (k=s*8+4+tig, n=g) per m16n8k8.row.col.
// ---------------------------------------------------------------------------
__global__ void prep_weights(const float* __restrict__ W,
                             uint32_t* __restrict__ out, int N, int K)
{
    int t = blockIdx.x * 256 + threadIdx.x;
    if (t >= N * K) return;
    int n = t % N, k = t / N;
    uint32_t v = f2tf32(W[(size_t)k * N + n]);
    int j = n >> 7, ng = (n >> 3) & 15, gb = n & 7;
    int c = k >> 5, s = (k >> 3) & 3, rb = (k >> 2) & 1, tig = k & 3;
    int nch = K >> 5;
    out[((size_t)(j * nch + c) << 12) + (ng * 4 + s) * 64 + gb * 8 + tig * 2 + rb] = v;
}

// ---------------------------------------------------------------------------
// prep_cmb: cmb[(w*12+h)*2401 + e] = mask[w][e] + bias_table[rel[e]][h]
// ---------------------------------------------------------------------------
__global__ void prep_cmb(const float* __restrict__ mask,
                         const float* __restrict__ bias_table,
                         const int* __restrict__ rel,
                         float* __restrict__ cmb)
{
    const int NE = NTOK * NTOK;
    int t = blockIdx.x * 256 + threadIdx.x;
    if (t >= NWIN * NHEADS * NE) return;
    int e = t % NE;
    int wh = t / NE;
    int h = wh % NHEADS, w = wh / NHEADS;
    cmb[t] = mask[(size_t)w * NE + e] + bias_table[rel[e] * NHEADS + h];
}

// ---------------------------------------------------------------------------
// Double-buffered TF32 tensor-core GEMM with bias:
//   C[M,N] = A[M,K] @ W^T + bias[N], weights pre-permuted (Bp).
// CTA 128x128, K-chunk 32, 256 threads (8 warps, 2m x 4n of 64x32).
// A: row-major tf32 in smem, stride 36 u32 (conflict-free frag reads + STS.128)
// B: cp.async of pre-permuted image (4 x 16B per thread = full 16 KB chunk),
//    LDS.64 frag reads.
// Requires M%128==0, N%128==0, K%32==0.
// ---------------------------------------------------------------------------
#define GBM 128
#define GBN 128
#define GBK 32
#define ASTR 36                 // u32 per A row
#define ABUF (GBM * ASTR)       // 4608 u32
#define BBUF (64 * 64)          // 4096 u32 = 16 KB per chunk image
#define GEMM_SMEM ((2 * ABUF + 2 * BBUF) * 4)   // 69632 B

__global__ __launch_bounds__(256, 2) void gemm_tc(
    const float* __restrict__ A, const uint32_t* __restrict__ Bp,
    const float* __restrict__ bias, float* __restrict__ C,
    int M, int N, int K)
{
    extern __shared__ uint32_t sm[];
    uint32_t* Asm = sm;                // 2 x ABUF
    uint32_t* Bsm = sm + 2 * ABUF;     // 2 x BBUF

    const int tid  = threadIdx.x;
    const int wid  = tid >> 5;
    const int lane = tid & 31;
    const int wm   = wid & 1;
    const int wn   = wid >> 1;
    const int g    = lane >> 2;
    const int tig  = lane & 3;
    const int rowBase = blockIdx.y * GBM;
    const int colBase = blockIdx.x * GBN;
    const int nch = K >> 5;

    float acc[4][4][4];
    #pragma unroll
    for (int i = 0; i < 4; i++)
        #pragma unroll
        for (int j = 0; j < 4; j++)
            #pragma unroll
            for (int r = 0; r < 4; r++) acc[i][j][r] = 0.f;

    const float* Ag = A + (size_t)rowBase * K;
    const uint32_t* Bg = Bp + ((size_t)blockIdx.x * nch << 12) + tid * 4;

    // ---- prologue: prefetch chunk 0 (A to regs, full B image via 4x cp.async)
    float4 va[4];
    #pragma unroll
    for (int i = 0; i < 4; i++) {
        int f = i * 256 + tid;
        va[i] = *reinterpret_cast<const float4*>(
            Ag + (size_t)(f >> 3) * K + (f & 7) * 4);
    }
    #pragma unroll
    for (int i = 0; i < 4; i++)
        cp_async16(smem_u32(Bsm + i * 1024 + tid * 4), Bg + i * 1024);
    cp_commit();

    for (int c = 0; c < nch; c++) {
        uint32_t* Ab = Asm + (c & 1) * ABUF;
        uint32_t* Bb = Bsm + (c & 1) * BBUF;

        // ---- STS A_c (convert regs -> tf32, STS.128, conflict-free)
        #pragma unroll
        for (int i = 0; i < 4; i++) {
            int f = i * 256 + tid;
            int row = f >> 3, c4 = f & 7;
            uint4 u;
            u.x = f2tf32(va[i].x); u.y = f2tf32(va[i].y);
            u.z = f2tf32(va[i].z); u.w = f2tf32(va[i].w);
            *reinterpret_cast<uint4*>(Ab + row * ASTR + c4 * 4) = u;
        }
        cp_wait_all();          // B_c arrived
        __syncthreads();        // buffer c fully visible; prev mma done

        // ---- prefetch chunk c+1 (overlaps the mma below)
        if (c + 1 < nch) {
            #pragma unroll
            for (int i = 0; i < 4; i++) {
                int f = i * 256 + tid;
                va[i] = *reinterpret_cast<const float4*>(
                    Ag + (size_t)(f >> 3) * K + (c + 1) * GBK + (f & 7) * 4);
            }
            uint32_t bdst = smem_u32(Bsm + ((c + 1) & 1) * BBUF + tid * 4);
            const uint32_t* bsrc = Bg + (size_t)(c + 1) * 4096;
            #pragma unroll
            for (int i = 0; i < 4; i++)
                cp_async16(bdst + i * 4096, bsrc + i * 1024);   // 1024 u32 = 4096 B
            cp_commit();
        }

        // ---- mma: 4 k-steps x (4 mf x 4 nf)
        #pragma unroll
        for (int s = 0; s < 4; s++) {
            uint32_t af[4][4], bf[4][2];
            #pragma unroll
            for (int mf = 0; mf < 4; mf++) {
                int r0 = (wm * 64 + mf * 16 + g) * ASTR + s * 8 + tig;
                af[mf][0] = Ab[r0];
                af[mf][1] = Ab[r0 + 8 * ASTR];
                af[mf][2] = Ab[r0 + 4];
                af[mf][3] = Ab[r0 + 8 * ASTR + 4];
            }
            #pragma unroll
            for (int nf = 0; nf < 4; nf++) {
                uint2 v = *reinterpret_cast<const uint2*>(
                    &Bb[((wn * 4 + nf) * 4 + s) * 64 + lane * 2]);
                bf[nf][0] = v.x; bf[nf][1] = v.y;
            }
            #pragma unroll
            for (int mf = 0; mf < 4; mf++)
                #pragma unroll
                for (int nf = 0; nf < 4; nf++)
                    mma_tf32(acc[mf][nf], af[mf], bf[nf]);
        }
    }

    // ---- epilogue: bias add + STG.64
    #pragma unroll
    for (int nf = 0; nf < 4; nf++) {
        int col = colBase + wn * 32 + nf * 8 + tig * 2;
        float2 bv = *reinterpret_cast<const float2*>(bias + col);
        #pragma unroll
        for (int mf = 0; mf < 4; mf++) {
            int row0 = rowBase + wm * 64 + mf * 16 + g;
            float2 v0 = { acc[mf][nf][0] + bv.x, acc[mf][nf][1] + bv.y };
            float2 v1 = { acc[mf][nf][2] + bv.x, acc[mf][nf][3] + bv.y };
            *reinterpret_cast<float2*>(C + (size_t)row0 * N + col)       = v0;
            *reinterpret_cast<float2*>(C + (size_t)(row0 + 8) * N + col) = v1;
        }
    }
}

// ---------------------------------------------------------------------------
// Fused window attention v2 — register-blocked, warp-per-row-group.
// Block = one (window b, head h), 256 threads (8 warps).
// Warp w owns rows n = w, w+8, ... (<=7 rows). Each lane caches K columns
// m=lane and m=lane+32 in registers (reused across the warp's rows); Q rows
// are broadcast LDS.128. PV reuses each V column load across the rows.
// ---------------------------------------------------------------------------
__global__ __launch_bounds__(256) void attn_kernel(
    const float* __restrict__ qp, const float* __restrict__ kvp,
    const float* __restrict__ cmb, float* __restrict__ ao)
{
    const int b   = blockIdx.x;
    const int h   = blockIdx.y;
    const int tid = threadIdx.x;
    const int wid = tid >> 5;
    const int lane = tid & 31;

    __shared__ float qs[64 * 36];     // stride 36 -> conflict-free frag reads
    __shared__ float ks[64 * 36];     // rows 49..63 read-but-unused (guarded)
    __shared__ float vs[64 * 36];
    __shared__ float sa[NTOK * NTOK];

    // ---- load q/k/v tiles (49 rows x 32, float4)
    for (int f = tid; f < NTOK * 8; f += 256) {
        int r = f >> 3, c4 = f & 7;
        size_t qoff  = (size_t)(b * NTOK + r) * DIMC + h * HD + c4 * 4;
        size_t kvoff = (size_t)(b * NTOK + r) * (2 * DIMC) + h * HD + c4 * 4;
        *reinterpret_cast<float4*>(qs + r * 36 + c4 * 4) =
            *reinterpret_cast<const float4*>(qp + qoff);
        *reinterpret_cast<float4*>(ks + r * 36 + c4 * 4) =
            *reinterpret_cast<const float4*>(kvp + kvoff);
        *reinterpret_cast<float4*>(vs + r * 36 + c4 * 4) =
            *reinterpret_cast<const float4*>(kvp + kvoff + DIMC);
    }
    __syncthreads();

    const float scale = 0.17677669529663687f;   // 32^{-1/2}
    const float* cb = cmb + (size_t)((b & (NWIN - 1)) * NHEADS + h) * (NTOK * NTOK);

    // ---- logits
    {
        float k0[32], k1[32];
        #pragma unroll
        for (int i = 0; i < 8; i++) {
            float4 x = *reinterpret_cast<const float4*>(ks + lane * 36 + i * 4);
            k0[i*4] = x.x; k0[i*4+1] = x.y; k0[i*4+2] = x.z; k0[i*4+3] = x.w;
            float4 y = *reinterpret_cast<const float4*>(ks + (lane + 32) * 36 + i * 4);
            k1[i*4] = y.x; k1[i*4+1] = y.y; k1[i*4+2] = y.z; k1[i*4+3] = y.w;
        }
        const bool m1ok = (lane + 32) < NTOK;
        #pragma unroll
        for (int r = 0; r < 7; r++) {
            int n = wid + 8 * r;
            if (n < NTOK) {
                float a0 = 0.f, a1 = 0.f;
                #pragma unroll
                for (int i = 0; i < 8; i++) {
                    float4 qv = *reinterpret_cast<const float4*>(qs + n * 36 + i * 4);
                    a0 = fmaf(qv.x, k0[i*4],   a0);
                    a0 = fmaf(qv.y, k0[i*4+1], a0);
                    a0 = fmaf(qv.z, k0[i*4+2], a0);
                    a0 = fmaf(qv.w, k0[i*4+3], a0);
                    a1 = fmaf(qv.x, k1[i*4],   a1);
                    a1 = fmaf(qv.y, k1[i*4+1], a1);
                    a1 = fmaf(qv.z, k1[i*4+2], a1);
                    a1 = fmaf(qv.w, k1[i*4+3], a1);
                }
                sa[n * NTOK + lane] = fmaf(a0, scale, cb[n * NTOK + lane]);
                if (m1ok)
                    sa[n * NTOK + lane + 32] =
                        fmaf(a1, scale, cb[n * NTOK + lane + 32]);
            }
        }
    }
    __syncthreads();

    // ---- softmax (warp-parallel per row)
    #pragma unroll
    for (int r = 0; r < 7; r++) {
        int n = wid + 8 * r;
        if (n < NTOK) {
            float x0 = sa[n * NTOK + lane];
            float x1 = (lane + 32 < NTOK) ? sa[n * NTOK + lane + 32] : -1e30f;
            float mx = fmaxf(x0, x1);
            #pragma unroll
            for (int o = 16; o > 0; o >>= 1)
                mx = fmaxf(mx, __shfl_xor_sync(0xFFFFFFFFu, mx, o));
            float e0 = __expf(x0 - mx);
            float e1 = (lane + 32 < NTOK) ? __expf(x1 - mx) : 0.f;
            float sum = e0 + e1;
            #pragma unroll
            for (int o = 16; o > 0; o >>= 1)
                sum += __shfl_xor_sync(0xFFFFFFFFu, sum, o);
            float inv = 1.f / sum;
            sa[n * NTOK + lane] = e0 * inv;
            if (lane + 32 < NTOK) sa[n * NTOK + lane + 32] = e1 * inv;
        }
    }
    __syncthreads();

    // ---- PV: lane = output channel d; reuse each V load across 7 rows
    {
        float accv[7];
        #pragma unroll
        for (int r = 0; r < 7; r++) accv[r] = 0.f;
        for (int m = 0; m < NTOK; m++) {
            float v = vs[m * 36 + lane];
            #pragma unroll
            for (int r = 0; r < 7; r++) {
                int n = wid + 8 * r;
                if (n < NTOK) accv[r] = fmaf(sa[n * NTOK + m], v, accv[r]);
            }
        }
        #pragma unroll
        for (int r = 0; r < 7; r++) {
            int n = wid + 8 * r;
            if (n < NTOK)
                ao[(size_t)(b * NTOK + n) * DIMC + h * HD + lane] = accv[r];
        }
    }
}

// ---------------------------------------------------------------------------
// Launch
// ---------------------------------------------------------------------------
extern "C" void kernel_launch(void* const* d_in, const int* in_sizes, int n_in,
                              void* d_out, int out_size)
{
    const float* q          = (const float*)d_in[0];
    const float* kv         = (const float*)d_in[1];
    const float* mask       = (const float*)d_in[2];
    const float* Wq         = (const float*)d_in[3];
    const float* bq         = (const float*)d_in[4];
    const float* Wkv        = (const float*)d_in[5];
    const float* bkv        = (const float*)d_in[6];
    const float* Wp         = (const float*)d_in[7];
    const float* bp         = (const float*)d_in[8];
    const float* bias_table = (const float*)d_in[9];
    const int*   rel_index  = (const int*)d_in[10];
    float*       out        = (float*)d_out;

    float *qp, *kvp, *ao, *cmb;
    uint32_t *wqp, *wkvp, *wpp;
    cudaGetSymbolAddress((void**)&qp,   g_qp);
    cudaGetSymbolAddress((void**)&kvp,  g_kv);
    cudaGetSymbolAddress((void**)&ao,   g_ao);
    cudaGetSymbolAddress((void**)&wqp,  g_wqp);
    cudaGetSymbolAddress((void**)&wkvp, g_wkvp);
    cudaGetSymbolAddress((void**)&wpp,  g_wpp);
    cudaGetSymbolAddress((void**)&cmb,  g_cmb);

    cudaFuncSetAttribute(gemm_tc,
                         cudaFuncAttributeMaxDynamicSharedMemorySize, GEMM_SMEM);

    // 0. weight permutation + combined bias table
    prep_weights<<<(DIMC * DIMC + 255) / 256, 256>>>(Wq, wqp, DIMC, DIMC);
    prep_weights<<<(2 * DIMC * DIMC + 255) / 256, 256>>>(Wkv, wkvp, 2 * DIMC, DIMC);
    prep_weights<<<(DIMC * DIMC + 255) / 256, 256>>>(Wp, wpp, DIMC, DIMC);
    prep_cmb<<<(NWIN * NHEADS * NTOK * NTOK + 255) / 256, 256>>>(
        mask, bias_table, rel_index, cmb);

    const int mblocks = MROWS / GBM;   // 1568

    // 1. q projection
    gemm_tc<<<dim3(DIMC / GBN, mblocks), 256, GEMM_SMEM>>>(
        q, wqp, bq, qp, MROWS, DIMC, DIMC);

    // 2. kv projection
    gemm_tc<<<dim3(2 * DIMC / GBN, mblocks), 256, GEMM_SMEM>>>(
        kv, wkvp, bkv, kvp, MROWS, 2 * DIMC, DIMC);

    // 3. fused window attention
    attn_kernel<<<dim3(BATCH, NHEADS), 256>>>(qp, kvp, cmb, ao);

    // 4. output projection
    gemm_tc<<<dim3(DIMC / GBN, mblocks), 256, GEMM_SMEM>>>(
        ao, wpp, bp, out, MROWS, DIMC, DIMC);
}

// round 16
// speedup vs baseline: 2.7664x; 1.0682x over previous
#include <cuda_runtime.h>
#include <cstdint>
#include <cstddef>

// ---------------------------------------------------------------------------
// Problem constants
// ---------------------------------------------------------------------------
#define DIMC   384
#define NHEADS 12
#define HD     32
#define NTOK   49
#define NWIN   64
#define BATCH  4096
#define MROWS  (BATCH * NTOK)   // 200704 = 128 * 1568

// ---------------------------------------------------------------------------
// Scratch (static device globals: allocation-guard safe)
// ---------------------------------------------------------------------------
__device__ float    g_qp[(size_t)MROWS * DIMC];
__device__ float    g_kv[(size_t)MROWS * 2 * DIMC];
__device__ float    g_ao[(size_t)MROWS * DIMC];
__device__ uint32_t g_wqp[DIMC * DIMC];            // Wq  fragment-major tf32
__device__ uint32_t g_wkvp[2 * DIMC * DIMC];       // Wkv fragment-major tf32
__device__ uint32_t g_wpp[DIMC * DIMC];            // Wp  fragment-major tf32
__device__ float    g_cmb[NWIN * NHEADS * NTOK * NTOK];  // mask+bias combined

// ---------------------------------------------------------------------------
// Helpers (baseline PTX only — plain sm_103 target)
// ---------------------------------------------------------------------------
__device__ __forceinline__ uint32_t f2tf32(float x) {
    uint32_t r;
    asm("cvt.rna.tf32.f32 %0, %1;" : "=r"(r) : "f"(x));
    return r;
}

__device__ __forceinline__ void mma_tf32(float c[4], const uint32_t a[4],
                                         const uint32_t b[2]) {
    asm volatile(
        "mma.sync.aligned.m16n8k8.row.col.f32.tf32.tf32.f32 "
        "{%0,%1,%2,%3}, {%4,%5,%6,%7}, {%8,%9}, {%0,%1,%2,%3};"
        : "+f"(c[0]), "+f"(c[1]), "+f"(c[2]), "+f"(c[3])
        : "r"(a[0]), "r"(a[1]), "r"(a[2]), "r"(a[3]), "r"(b[0]), "r"(b[1]));
}

__device__ __forceinline__ uint32_t smem_u32(const void* p) {
    uint32_t a;
    asm("{ .reg .u64 t; cvta.to.shared.u64 t, %1; cvt.u32.u64 %0, t; }"
        : "=r"(a) : "l"(p));
    return a;
}

__device__ __forceinline__ void cp_async16(uint32_t dst_smem, const void* src) {
    asm volatile("cp.async.cg.shared.global [%0], [%1], 16;"
                 :: "r"(dst_smem), "l"(src) : "memory");
}
__device__ __forceinline__ void cp_commit() {
    asm volatile("cp.async.commit_group;" ::: "memory");
}

// ---------------------------------------------------------------------------
// prep_weights: W row-major [K,N] -> fragment-major tf32 global.
// Per (n-block j of 128, k-chunk c of 32): 4096-u32 image, index
//   (ng*4 + s)*64 + gb*8 + tig*2 + rb
// with ng=(n>>3)&15, gb=n&7, s=(k>>3)&3, rb=(k>>2)&1, tig=k&3.
// ---------------------------------------------------------------------------
__global__ void prep_weights(const float* __restrict__ W,
                             uint32_t* __restrict__ out, int N, int K)
{
    int t = blockIdx.x * 256 + threadIdx.x;
    if (t >= N * K) return;
    int n = t % N, k = t / N;
    uint32_t v = f2tf32(W[(size_t)k * N + n]);
    int j = n >> 7, ng = (n >> 3) & 15, gb = n & 7;
    int c = k >> 5, s = (k >> 3) & 3, rb = (k >> 2) & 1, tig = k & 3;
    int nch = K >> 5;
    out[((size_t)(j * nch + c) << 12) + (ng * 4 + s) * 64 + gb * 8 + tig * 2 + rb] = v;
}

// ---------------------------------------------------------------------------
// prep_cmb: cmb[(w*12+h)*2401 + e] = mask[w][e] + bias_table[rel[e]][h]
// ---------------------------------------------------------------------------
__global__ void prep_cmb(const float* __restrict__ mask,
                         const float* __restrict__ bias_table,
                         const int* __restrict__ rel,
                         float* __restrict__ cmb)
{
    const int NE = NTOK * NTOK;
    int t = blockIdx.x * 256 + threadIdx.x;
    if (t >= NWIN * NHEADS * NE) return;
    int e = t % NE;
    int wh = t / NE;
    int h = wh % NHEADS, w = wh / NHEADS;
    cmb[t] = mask[(size_t)w * NE + e] + bias_table[rel[e] * NHEADS + h];
}

// ---------------------------------------------------------------------------
// 3-stage cp.async pipelined TF32 tensor-core GEMM with bias:
//   C[M,N] = A[M,K] @ W^T + bias[N], weights pre-permuted (Bp).
// CTA 128x128, K-chunk 32, 256 threads (8 warps, 2m x 4n of 64x32).
// A staged as raw fp32 (row-major, stride 36) via cp.async; cvt.rna at
// fragment-read. B staged as pre-permuted tf32 image via cp.async.
// One wait_group(1) + one __syncthreads per chunk; empty commits keep the
// group count uniform through the tail.
// Requires M%128==0, N%128==0, K%32==0.
// ---------------------------------------------------------------------------
#define GBM 128
#define GBN 128
#define GBK 32
#define ASTR 36                    // u32 per A row (conflict-free frag reads)
#define ABUFU (GBM * ASTR)         // 4608 u32
#define BBUFU 4096                 // 16 KB B chunk image
#define NST 3
#define STAGEU (ABUFU + BBUFU)     // 8704 u32 = 34816 B
#define GEMM_SMEM (NST * STAGEU * 4)   // 104448 B

__global__ __launch_bounds__(256, 2) void gemm_tc(
    const float* __restrict__ A, const uint32_t* __restrict__ Bp,
    const float* __restrict__ bias, float* __restrict__ C,
    int M, int N, int K)
{
    extern __shared__ uint32_t sm[];

    const int tid  = threadIdx.x;
    const int wid  = tid >> 5;
    const int lane = tid & 31;
    const int wm   = wid & 1;
    const int wn   = wid >> 1;
    const int g    = lane >> 2;
    const int tig  = lane & 3;
    const int rowBase = blockIdx.y * GBM;
    const int colBase = blockIdx.x * GBN;
    const int nch = K >> 5;

    float acc[4][4][4];
    #pragma unroll
    for (int i = 0; i < 4; i++)
        #pragma unroll
        for (int j = 0; j < 4; j++)
            #pragma unroll
            for (int r = 0; r < 4; r++) acc[i][j][r] = 0.f;

    const float* Ag = A + (size_t)rowBase * K;
    const uint32_t* Bg = Bp + ((size_t)blockIdx.x * nch << 12);

    // per-thread fixed assignments for the stage fill
    const int arow = tid >> 1;              // with i-offset: rows covered below
    (void)arow;

    // issue chunk c into stage c%NST (8 x 16B per thread = A 16KB + B 16KB)
    auto issue = [&](int c) {
        uint32_t* st = sm + (c % NST) * STAGEU;
        #pragma unroll
        for (int i = 0; i < 4; i++) {
            int f   = i * 256 + tid;        // 1024 16B chunks of A
            int row = f >> 3, c4 = f & 7;
            cp_async16(smem_u32(st + row * ASTR + c4 * 4),
                       Ag + (size_t)row * K + c * GBK + c4 * 4);
        }
        uint32_t bdst = smem_u32(st + ABUFU + tid * 4);
        const uint32_t* bsrc = Bg + ((size_t)c << 12) + tid * 4;
        #pragma unroll
        for (int i = 0; i < 4; i++)
            cp_async16(bdst + i * 4096, bsrc + i * 1024);
    };

    // prologue: stages 0..NST-2 in flight
    #pragma unroll
    for (int c = 0; c < NST - 1; c++) { issue(c); cp_commit(); }

    for (int c = 0; c < nch; c++) {
        asm volatile("cp.async.wait_group %0;" :: "n"(NST - 2));
        __syncthreads();                    // stage c resident for all warps
        uint32_t* Ab = sm + (c % NST) * STAGEU;
        uint32_t* Bb = Ab + ABUFU;

        // refill: writes stage (c-1)%NST, whose readers all passed the sync
        if (c + NST - 1 < nch) issue(c + NST - 1);
        cp_commit();                        // unconditional: uniform group count

        #pragma unroll
        for (int s = 0; s < 4; s++) {
            uint32_t af[4][4], bf[4][2];
            #pragma unroll
            for (int mf = 0; mf < 4; mf++) {
                int r0 = (wm * 64 + mf * 16 + g) * ASTR + s * 8 + tig;
                af[mf][0] = f2tf32(__uint_as_float(Ab[r0]));
                af[mf][1] = f2tf32(__uint_as_float(Ab[r0 + 8 * ASTR]));
                af[mf][2] = f2tf32(__uint_as_float(Ab[r0 + 4]));
                af[mf][3] = f2tf32(__uint_as_float(Ab[r0 + 8 * ASTR + 4]));
            }
            #pragma unroll
            for (int nf = 0; nf < 4; nf++) {
                uint2 v = *reinterpret_cast<const uint2*>(
                    &Bb[((wn * 4 + nf) * 4 + s) * 64 + lane * 2]);
                bf[nf][0] = v.x; bf[nf][1] = v.y;
            }
            #pragma unroll
            for (int mf = 0; mf < 4; mf++)
                #pragma unroll
                for (int nf = 0; nf < 4; nf++)
                    mma_tf32(acc[mf][nf], af[mf], bf[nf]);
        }
    }

    // ---- epilogue: bias add + STG.64
    #pragma unroll
    for (int nf = 0; nf < 4; nf++) {
        int col = colBase + wn * 32 + nf * 8 + tig * 2;
        float2 bv = *reinterpret_cast<const float2*>(bias + col);
        #pragma unroll
        for (int mf = 0; mf < 4; mf++) {
            int row0 = rowBase + wm * 64 + mf * 16 + g;
            float2 v0 = { acc[mf][nf][0] + bv.x, acc[mf][nf][1] + bv.y };
            float2 v1 = { acc[mf][nf][2] + bv.x, acc[mf][nf][3] + bv.y };
            *reinterpret_cast<float2*>(C + (size_t)row0 * N + col)       = v0;
            *reinterpret_cast<float2*>(C + (size_t)(row0 + 8) * N + col) = v1;
        }
    }
}

// ---------------------------------------------------------------------------
// Fused window attention v3 — register-blocked, float4-broadcast PV.
// Block = one (window b, head h), 256 threads (8 warps).
// Warp w owns rows n = w, w+8, ... (<=7 rows). sa rows padded to stride 52
// (16B-aligned) so probability rows read as broadcast LDS.128.
// ---------------------------------------------------------------------------
#define SAS 52   // sa row stride (floats); 52*4=208 B, 16B-aligned

__global__ __launch_bounds__(256) void attn_kernel(
    const float* __restrict__ qp, const float* __restrict__ kvp,
    const float* __restrict__ cmb, float* __restrict__ ao)
{
    const int b   = blockIdx.x;
    const int h   = blockIdx.y;
    const int tid = threadIdx.x;
    const int wid = tid >> 5;
    const int lane = tid & 31;

    __shared__ __align__(16) float qs[64 * 36];
    __shared__ __align__(16) float ks[64 * 36];
    __shared__ __align__(16) float vs[64 * 36];
    __shared__ __align__(16) float sa[NTOK * SAS];

    // ---- load q/k/v tiles (49 rows x 32, float4)
    for (int f = tid; f < NTOK * 8; f += 256) {
        int r = f >> 3, c4 = f & 7;
        size_t qoff  = (size_t)(b * NTOK + r) * DIMC + h * HD + c4 * 4;
        size_t kvoff = (size_t)(b * NTOK + r) * (2 * DIMC) + h * HD + c4 * 4;
        *reinterpret_cast<float4*>(qs + r * 36 + c4 * 4) =
            *reinterpret_cast<const float4*>(qp + qoff);
        *reinterpret_cast<float4*>(ks + r * 36 + c4 * 4) =
            *reinterpret_cast<const float4*>(kvp + kvoff);
        *reinterpret_cast<float4*>(vs + r * 36 + c4 * 4) =
            *reinterpret_cast<const float4*>(kvp + kvoff + DIMC);
    }
    __syncthreads();

    const float scale = 0.17677669529663687f;   // 32^{-1/2}
    const float* cb = cmb + (size_t)((b & (NWIN - 1)) * NHEADS + h) * (NTOK * NTOK);

    // ---- logits (lane caches K columns m=lane, m=lane+32 in registers)
    {
        float k0[32], k1[32];
        #pragma unroll
        for (int i = 0; i < 8; i++) {
            float4 x = *reinterpret_cast<const float4*>(ks + lane * 36 + i * 4);
            k0[i*4] = x.x; k0[i*4+1] = x.y; k0[i*4+2] = x.z; k0[i*4+3] = x.w;
            float4 y = *reinterpret_cast<const float4*>(ks + (lane + 32) * 36 + i * 4);
            k1[i*4] = y.x; k1[i*4+1] = y.y; k1[i*4+2] = y.z; k1[i*4+3] = y.w;
        }
        const bool m1ok = (lane + 32) < NTOK;
        #pragma unroll
        for (int r = 0; r < 7; r++) {
            int n = wid + 8 * r;
            if (n < NTOK) {
                float a0 = 0.f, a1 = 0.f;
                #pragma unroll
                for (int i = 0; i < 8; i++) {
                    float4 qv = *reinterpret_cast<const float4*>(qs + n * 36 + i * 4);
                    a0 = fmaf(qv.x, k0[i*4],   a0);
                    a0 = fmaf(qv.y, k0[i*4+1], a0);
                    a0 = fmaf(qv.z, k0[i*4+2], a0);
                    a0 = fmaf(qv.w, k0[i*4+3], a0);
                    a1 = fmaf(qv.x, k1[i*4],   a1);
                    a1 = fmaf(qv.y, k1[i*4+1], a1);
                    a1 = fmaf(qv.z, k1[i*4+2], a1);
                    a1 = fmaf(qv.w, k1[i*4+3], a1);
                }
                sa[n * SAS + lane] = fmaf(a0, scale, cb[n * NTOK + lane]);
                if (m1ok)
                    sa[n * SAS + lane + 32] =
                        fmaf(a1, scale, cb[n * NTOK + lane + 32]);
            }
        }
    }
    __syncthreads();

    // ---- softmax (warp-parallel per row)
    #pragma unroll
    for (int r = 0; r < 7; r++) {
        int n = wid + 8 * r;
        if (n < NTOK) {
            float x0 = sa[n * SAS + lane];
            float x1 = (lane + 32 < NTOK) ? sa[n * SAS + lane + 32] : -1e30f;
            float mx = fmaxf(x0, x1);
            #pragma unroll
            for (int o = 16; o > 0; o >>= 1)
                mx = fmaxf(mx, __shfl_xor_sync(0xFFFFFFFFu, mx, o));
            float e0 = __expf(x0 - mx);
            float e1 = (lane + 32 < NTOK) ? __expf(x1 - mx) : 0.f;
            float sum = e0 + e1;
            #pragma unroll
            for (int o = 16; o > 0; o >>= 1)
                sum += __shfl_xor_sync(0xFFFFFFFFu, sum, o);
            float inv = 1.f / sum;
            sa[n * SAS + lane] = e0 * inv;
            if (lane + 32 < NTOK) sa[n * SAS + lane + 32] = e1 * inv;
        }
    }
    __syncthreads();

    // ---- PV: lane = output channel d; m-blocks of 4, probabilities read as
    //      broadcast LDS.128, V scalars shared across the warp's 7 rows
    {
        float accv[7];
        #pragma unroll
        for (int r = 0; r < 7; r++) accv[r] = 0.f;

        #pragma unroll
        for (int m4 = 0; m4 < 48; m4 += 4) {
            float v0 = vs[(m4 + 0) * 36 + lane];
            float v1 = vs[(m4 + 1) * 36 + lane];
            float v2 = vs[(m4 + 2) * 36 + lane];
            float v3 = vs[(m4 + 3) * 36 + lane];
            #pragma unroll
            for (int r = 0; r < 7; r++) {
                int n = wid + 8 * r;
                if (n < NTOK) {
                    float4 p = *reinterpret_cast<const float4*>(sa + n * SAS + m4);
                    accv[r] = fmaf(p.x, v0, accv[r]);
                    accv[r] = fmaf(p.y, v1, accv[r]);
                    accv[r] = fmaf(p.z, v2, accv[r]);
                    accv[r] = fmaf(p.w, v3, accv[r]);
                }
            }
        }
        {   // m = 48 remainder
            float v48 = vs[48 * 36 + lane];
            #pragma unroll
            for (int r = 0; r < 7; r++) {
                int n = wid + 8 * r;
                if (n < NTOK) accv[r] = fmaf(sa[n * SAS + 48], v48, accv[r]);
            }
        }
        #pragma unroll
        for (int r = 0; r < 7; r++) {
            int n = wid + 8 * r;
            if (n < NTOK)
                ao[(size_t)(b * NTOK + n) * DIMC + h * HD + lane] = accv[r];
        }
    }
}

// ---------------------------------------------------------------------------
// Launch
// ---------------------------------------------------------------------------
extern "C" void kernel_launch(void* const* d_in, const int* in_sizes, int n_in,
                              void* d_out, int out_size)
{
    const float* q          = (const float*)d_in[0];
    const float* kv         = (const float*)d_in[1];
    const float* mask       = (const float*)d_in[2];
    const float* Wq         = (const float*)d_in[3];
    const float* bq         = (const float*)d_in[4];
    const float* Wkv        = (const float*)d_in[5];
    const float* bkv        = (const float*)d_in[6];
    const float* Wp         = (const float*)d_in[7];
    const float* bp         = (const float*)d_in[8];
    const float* bias_table = (const float*)d_in[9];
    const int*   rel_index  = (const int*)d_in[10];
    float*       out        = (float*)d_out;

    float *qp, *kvp, *ao, *cmb;
    uint32_t *wqp, *wkvp, *wpp;
    cudaGetSymbolAddress((void**)&qp,   g_qp);
    cudaGetSymbolAddress((void**)&kvp,  g_kv);
    cudaGetSymbolAddress((void**)&ao,   g_ao);
    cudaGetSymbolAddress((void**)&wqp,  g_wqp);
    cudaGetSymbolAddress((void**)&wkvp, g_wkvp);
    cudaGetSymbolAddress((void**)&wpp,  g_wpp);
    cudaGetSymbolAddress((void**)&cmb,  g_cmb);

    cudaFuncSetAttribute(gemm_tc,
                         cudaFuncAttributeMaxDynamicSharedMemorySize, GEMM_SMEM);

    // 0. weight permutation + combined bias table
    prep_weights<<<(DIMC * DIMC + 255) / 256, 256>>>(Wq, wqp, DIMC, DIMC);
    prep_weights<<<(2 * DIMC * DIMC + 255) / 256, 256>>>(Wkv, wkvp, 2 * DIMC, DIMC);
    prep_weights<<<(DIMC * DIMC + 255) / 256, 256>>>(Wp, wpp, DIMC, DIMC);
    prep_cmb<<<(NWIN * NHEADS * NTOK * NTOK + 255) / 256, 256>>>(
        mask, bias_table, rel_index, cmb);

    const int mblocks = MROWS / GBM;   // 1568

    // 1. q projection
    gemm_tc<<<dim3(DIMC / GBN, mblocks), 256, GEMM_SMEM>>>(
        q, wqp, bq, qp, MROWS, DIMC, DIMC);

    // 2. kv projection
    gemm_tc<<<dim3(2 * DIMC / GBN, mblocks), 256, GEMM_SMEM>>>(
        kv, wkvp, bkv, kvp, MROWS, 2 * DIMC, DIMC);

    // 3. fused window attention
    attn_kernel<<<dim3(BATCH, NHEADS), 256>>>(qp, kvp, cmb, ao);

    // 4. output projection
    gemm_tc<<<dim3(DIMC / GBN, mblocks), 256, GEMM_SMEM>>>(
        ao, wpp, bp, out, MROWS, DIMC, DIMC);
}